// round 8
// baseline (speedup 1.0000x reference)
#include <cuda_runtime.h>
#include <cuda_fp16.h>

#define BB 128
#define LL 512
#define KN 8
#define DD 300
#define CC 14
#define LCHUNK 64
#define NCHUNK (LL / LCHUNK)   // 8
#define NROWS 4905             // NUM_NODES + 1
#define RSTRIDE 320            // halves per row: 640B = 5 x 128B sectors
#define RH2 (RSTRIDE / 2)      // 160 half2 per row
#define CVT_WARPS 16

// fp16 copy of R, row-padded for sector alignment
__device__ __half2 g_Rh2[NROWS * RH2];
// Deterministic partial-sum scratch: [chunk][b][d]
__device__ float g_part[NCHUNK * BB * DD];

__global__ __launch_bounds__(CVT_WARPS * 32)
void convert_kernel(const float* __restrict__ R)
{
    const int wid  = threadIdx.x >> 5;
    const int lane = threadIdx.x & 31;
    const int row  = blockIdx.x * CVT_WARPS + wid;
    if (row >= NROWS) return;

    // Each warp converts one row: lane covers t = lane + j*32, j<5 (t<150 used)
    const float* src = R + row * DD;
    __half2*     dst = g_Rh2 + row * RH2;

    float2 v[5];
    #pragma unroll
    for (int j = 0; j < 5; ++j) {
        const int t = lane + j * 32;
        v[j] = (t < DD / 2) ? *(const float2*)&src[t * 2] : make_float2(0.f, 0.f);
    }
    #pragma unroll
    for (int j = 0; j < 5; ++j) {
        const int t = lane + j * 32;
        if (t < RH2)
            dst[t] = __floats2half2_rn(v[j].x, v[j].y);
    }
}

__global__ __launch_bounds__(160)
void gnn_pool_kernel(const int* __restrict__ master,
                     const int* __restrict__ slave,
                     const int* __restrict__ edge,
                     const float* __restrict__ E,
                     const float* __restrict__ Ngate)
{
    const int b     = blockIdx.y;
    const int chunk = blockIdx.x;
    const int tid   = threadIdx.x;

    __shared__ __align__(16) int   s_node[LCHUNK * KN];  // pre-scaled half2 offsets
    __shared__ __align__(16) float s_e[LCHUNK * KN];
    __shared__ int   s_m[LCHUNK];                        // pre-scaled
    __shared__ float s_g[LCHUNK];

    const int base = b * LL + chunk * LCHUNK;

    for (int i = tid; i < LCHUNK * KN; i += 160) {
        const int pos = base + (i >> 3);
        const int k   = i & 7;
        s_node[i] = slave[pos * KN + k] * RH2;
        s_e[i]    = E[edge[pos * KN + k]];
    }
    if (tid < LCHUNK) {
        const int m = master[base + tid];
        s_m[tid] = m * RH2;
        s_g[tid] = Ngate[m];
    }
    __syncthreads();

    if (tid >= 150) return;   // 150 half2 lanes cover 300 dims

    const __half2* Rbase = g_Rh2 + tid;
    float2 acc = make_float2(0.f, 0.f);

    #pragma unroll 4
    for (int li = 0; li < LCHUNK; ++li) {
        const int4   n0 = *(const int4*)  &s_node[li * KN];
        const int4   n1 = *(const int4*)  &s_node[li * KN + 4];
        const float4 e0 = *(const float4*)&s_e[li * KN];
        const float4 e1 = *(const float4*)&s_e[li * KN + 4];

        const float2 f0 = __half22float2(Rbase[n0.x]);
        const float2 f1 = __half22float2(Rbase[n0.y]);
        const float2 f2 = __half22float2(Rbase[n0.z]);
        const float2 f3 = __half22float2(Rbase[n0.w]);
        const float2 f4 = __half22float2(Rbase[n1.x]);
        const float2 f5 = __half22float2(Rbase[n1.y]);
        const float2 f6 = __half22float2(Rbase[n1.z]);
        const float2 f7 = __half22float2(Rbase[n1.w]);
        const float2 fm = __half22float2(Rbase[s_m[li]]);

        float mx0 = f0.x * e0.x;
        float mx1 = f0.y * e0.x;
        mx0 = fmaxf(mx0, f1.x * e0.y);  mx1 = fmaxf(mx1, f1.y * e0.y);
        mx0 = fmaxf(mx0, f2.x * e0.z);  mx1 = fmaxf(mx1, f2.y * e0.z);
        mx0 = fmaxf(mx0, f3.x * e0.w);  mx1 = fmaxf(mx1, f3.y * e0.w);
        mx0 = fmaxf(mx0, f4.x * e1.x);  mx1 = fmaxf(mx1, f4.y * e1.x);
        mx0 = fmaxf(mx0, f5.x * e1.y);  mx1 = fmaxf(mx1, f5.y * e1.y);
        mx0 = fmaxf(mx0, f6.x * e1.z);  mx1 = fmaxf(mx1, f6.y * e1.z);
        mx0 = fmaxf(mx0, f7.x * e1.w);  mx1 = fmaxf(mx1, f7.y * e1.w);

        const float g = s_g[li];
        acc.x += mx0 + g * (fm.x - mx0);
        acc.y += mx1 + g * (fm.y - mx1);
    }

    float2* outp = (float2*)&g_part[(chunk * BB + b) * DD];
    outp[tid] = acc;
}

__global__ __launch_bounds__(448)
void head_kernel(const float* __restrict__ W,
                 const float* __restrict__ bias,
                 float* __restrict__ out)
{
    const int b    = blockIdx.x;
    const int tid  = threadIdx.x;
    const int wid  = tid >> 5;
    const int lane = tid & 31;

    __shared__ float sh[CC];

    // One warp per class: fused chunk-reduce + FC (no smem staging phase)
    if (wid < CC) {
        const float* Wc = W + wid * DD;
        float s = 0.f;
        #pragma unroll
        for (int it = 0; it < 10; ++it) {
            const int d = lane + it * 32;
            if (d < DD) {
                float xd = 0.f;
                #pragma unroll
                for (int c = 0; c < NCHUNK; ++c)
                    xd += g_part[(c * BB + b) * DD + d];
                s += xd * Wc[d];
            }
        }
        #pragma unroll
        for (int off = 16; off; off >>= 1)
            s += __shfl_down_sync(0xffffffffu, s, off);
        if (lane == 0)
            sh[wid] = fmaxf(s + bias[wid], 0.f);
    }
    __syncthreads();

    // Parallel softmax over 14 classes (warp 0)
    if (wid == 0) {
        const float h = (lane < CC) ? sh[lane] : -1e30f;
        float m = h;
        #pragma unroll
        for (int off = 16; off; off >>= 1)
            m = fmaxf(m, __shfl_xor_sync(0xffffffffu, m, off));
        const float e = (lane < CC) ? expf(h - m) : 0.f;
        float sum = e;
        #pragma unroll
        for (int off = 16; off; off >>= 1)
            sum += __shfl_xor_sync(0xffffffffu, sum, off);
        if (lane < CC)
            out[b * CC + lane] = e / sum;
    }
}

extern "C" void kernel_launch(void* const* d_in, const int* in_sizes, int n_in,
                              void* d_out, int out_size)
{
    const int*   master = (const int*)  d_in[0];
    const int*   slave  = (const int*)  d_in[1];
    const int*   edge   = (const int*)  d_in[2];
    const float* R      = (const float*)d_in[3];
    const float* E      = (const float*)d_in[4];
    const float* Ngate  = (const float*)d_in[5];
    const float* W      = (const float*)d_in[6];
    const float* bias   = (const float*)d_in[7];
    float* out = (float*)d_out;

    convert_kernel<<<(NROWS + CVT_WARPS - 1) / CVT_WARPS, CVT_WARPS * 32>>>(R);
    gnn_pool_kernel<<<dim3(NCHUNK, BB), 160>>>(master, slave, edge, E, Ngate);
    head_kernel<<<BB, 448>>>(W, bias, out);
}

// round 9
// speedup vs baseline: 1.0050x; 1.0050x over previous
#include <cuda_runtime.h>
#include <cuda_fp16.h>

#define BB 128
#define LL 512
#define KN 8
#define DD 300
#define CC 14
#define LCHUNK 64
#define NCHUNK (LL / LCHUNK)   // 8
#define NPOS (BB * LL)         // 65536 positions
#define NJOB (NPOS / LCHUNK)   // 1024 metadata jobs
#define NROWS 4905             // NUM_NODES + 1
#define RSTRIDE 320            // halves per row: 640B = 5 x 128B sectors
#define RH2 (RSTRIDE / 2)      // 160 half2 per row
#define CVT_WARPS 16
#define CVT_BLKS ((NROWS + CVT_WARPS - 1) / CVT_WARPS)   // 307

// fp16 copy of R, row-padded for sector alignment
__device__ __half2 g_Rh2[NROWS * RH2];
// Deterministic partial-sum scratch: [chunk][b][d]
__device__ float g_part[NCHUNK * BB * DD];
// Precomputed metadata (written by prep, read coalesced by pool)
__device__ int   g_node[NPOS * KN];   // slave index pre-scaled to half2 offset
__device__ float g_e[NPOS * KN];      // E[edge]
__device__ int   g_m[NPOS];           // master index pre-scaled
__device__ float g_g[NPOS];           // Ngate[master]

__global__ __launch_bounds__(512)
void prep_kernel(const float* __restrict__ R,
                 const int*   __restrict__ master,
                 const int*   __restrict__ slave,
                 const int*   __restrict__ edge,
                 const float* __restrict__ E,
                 const float* __restrict__ Ngate)
{
    if (blockIdx.x < CVT_BLKS) {
        // ---- convert role: one warp per R row ----
        const int wid  = threadIdx.x >> 5;
        const int lane = threadIdx.x & 31;
        const int row  = blockIdx.x * CVT_WARPS + wid;
        if (row >= NROWS) return;

        const float* src = R + row * DD;
        __half2*     dst = g_Rh2 + row * RH2;

        float2 v[5];
        #pragma unroll
        for (int j = 0; j < 5; ++j) {
            const int t = lane + j * 32;
            v[j] = (t < DD / 2) ? *(const float2*)&src[t * 2]
                                : make_float2(0.f, 0.f);
        }
        #pragma unroll
        for (int j = 0; j < 5; ++j) {
            const int t = lane + j * 32;
            if (t < RH2)
                dst[t] = __floats2half2_rn(v[j].x, v[j].y);
        }
    } else {
        // ---- metadata role: one block per 64-position job ----
        const int job  = blockIdx.x - CVT_BLKS;     // 0..NJOB-1
        const int base = job * LCHUNK;              // first position
        const int t    = threadIdx.x;               // 512 threads = 512 entries

        const int idx = base * KN + t;
        g_node[idx] = slave[idx] * RH2;
        g_e[idx]    = E[edge[idx]];

        if (t < LCHUNK) {
            const int p = base + t;
            const int m = master[p];
            g_m[p] = m * RH2;
            g_g[p] = Ngate[m];
        }
    }
}

__global__ __launch_bounds__(160)
void gnn_pool_kernel()
{
    const int b     = blockIdx.y;
    const int chunk = blockIdx.x;
    const int tid   = threadIdx.x;

    __shared__ __align__(16) int   s_node[LCHUNK * KN];
    __shared__ __align__(16) float s_e[LCHUNK * KN];
    __shared__ int   s_m[LCHUNK];
    __shared__ float s_g[LCHUNK];

    const int base = b * LL + chunk * LCHUNK;

    // Coalesced copy of precomputed metadata (no random gathers here)
    #pragma unroll
    for (int r = 0; r < 4; ++r) {
        const int i = tid + r * 160;
        if (i < LCHUNK * KN) {
            s_node[i] = g_node[base * KN + i];
            s_e[i]    = g_e[base * KN + i];
        }
    }
    if (tid < LCHUNK) {
        s_m[tid] = g_m[base + tid];
        s_g[tid] = g_g[base + tid];
    }
    __syncthreads();

    if (tid >= 150) return;   // 150 half2 lanes cover 300 dims

    const __half2* Rbase = g_Rh2 + tid;
    float2 acc = make_float2(0.f, 0.f);

    #pragma unroll 4
    for (int li = 0; li < LCHUNK; ++li) {
        const int4   n0 = *(const int4*)  &s_node[li * KN];
        const int4   n1 = *(const int4*)  &s_node[li * KN + 4];
        const float4 e0 = *(const float4*)&s_e[li * KN];
        const float4 e1 = *(const float4*)&s_e[li * KN + 4];

        const float2 f0 = __half22float2(Rbase[n0.x]);
        const float2 f1 = __half22float2(Rbase[n0.y]);
        const float2 f2 = __half22float2(Rbase[n0.z]);
        const float2 f3 = __half22float2(Rbase[n0.w]);
        const float2 f4 = __half22float2(Rbase[n1.x]);
        const float2 f5 = __half22float2(Rbase[n1.y]);
        const float2 f6 = __half22float2(Rbase[n1.z]);
        const float2 f7 = __half22float2(Rbase[n1.w]);
        const float2 fm = __half22float2(Rbase[s_m[li]]);

        float mx0 = f0.x * e0.x;
        float mx1 = f0.y * e0.x;
        mx0 = fmaxf(mx0, f1.x * e0.y);  mx1 = fmaxf(mx1, f1.y * e0.y);
        mx0 = fmaxf(mx0, f2.x * e0.z);  mx1 = fmaxf(mx1, f2.y * e0.z);
        mx0 = fmaxf(mx0, f3.x * e0.w);  mx1 = fmaxf(mx1, f3.y * e0.w);
        mx0 = fmaxf(mx0, f4.x * e1.x);  mx1 = fmaxf(mx1, f4.y * e1.x);
        mx0 = fmaxf(mx0, f5.x * e1.y);  mx1 = fmaxf(mx1, f5.y * e1.y);
        mx0 = fmaxf(mx0, f6.x * e1.z);  mx1 = fmaxf(mx1, f6.y * e1.z);
        mx0 = fmaxf(mx0, f7.x * e1.w);  mx1 = fmaxf(mx1, f7.y * e1.w);

        const float g = s_g[li];
        acc.x += mx0 + g * (fm.x - mx0);
        acc.y += mx1 + g * (fm.y - mx1);
    }

    float2* outp = (float2*)&g_part[(chunk * BB + b) * DD];
    outp[tid] = acc;
}

__global__ __launch_bounds__(448)
void head_kernel(const float* __restrict__ W,
                 const float* __restrict__ bias,
                 float* __restrict__ out)
{
    const int b    = blockIdx.x;
    const int tid  = threadIdx.x;
    const int wid  = tid >> 5;
    const int lane = tid & 31;

    __shared__ float sx[DD];
    __shared__ float sh[CC];

    // Reduce the 8 partials -> X[b][:]  (150 float2 lanes)
    if (tid < 150) {
        float2 s = make_float2(0.f, 0.f);
        #pragma unroll
        for (int c = 0; c < NCHUNK; ++c) {
            const float2 p = *(const float2*)&g_part[(c * BB + b) * DD + tid * 2];
            s.x += p.x;
            s.y += p.y;
        }
        sx[tid * 2]     = s.x;
        sx[tid * 2 + 1] = s.y;
    }
    __syncthreads();

    // One warp per class: h[c] = relu(X . W[c] + bias[c])
    if (wid < CC) {
        float s = 0.f;
        #pragma unroll
        for (int it = 0; it < 10; ++it) {
            const int d = lane + it * 32;
            if (d < DD) s += sx[d] * W[wid * DD + d];
        }
        #pragma unroll
        for (int off = 16; off; off >>= 1)
            s += __shfl_down_sync(0xffffffffu, s, off);
        if (lane == 0)
            sh[wid] = fmaxf(s + bias[wid], 0.f);
    }
    __syncthreads();

    // Parallel softmax over 14 classes (warp 0)
    if (wid == 0) {
        const float h = (lane < CC) ? sh[lane] : -1e30f;
        float m = h;
        #pragma unroll
        for (int off = 16; off; off >>= 1)
            m = fmaxf(m, __shfl_xor_sync(0xffffffffu, m, off));
        const float e = (lane < CC) ? expf(h - m) : 0.f;
        float sum = e;
        #pragma unroll
        for (int off = 16; off; off >>= 1)
            sum += __shfl_xor_sync(0xffffffffu, sum, off);
        if (lane < CC)
            out[b * CC + lane] = e / sum;
    }
}

extern "C" void kernel_launch(void* const* d_in, const int* in_sizes, int n_in,
                              void* d_out, int out_size)
{
    const int*   master = (const int*)  d_in[0];
    const int*   slave  = (const int*)  d_in[1];
    const int*   edge   = (const int*)  d_in[2];
    const float* R      = (const float*)d_in[3];
    const float* E      = (const float*)d_in[4];
    const float* Ngate  = (const float*)d_in[5];
    const float* W      = (const float*)d_in[6];
    const float* bias   = (const float*)d_in[7];
    float* out = (float*)d_out;

    prep_kernel<<<CVT_BLKS + NJOB, 512>>>(R, master, slave, edge, E, Ngate);
    gnn_pool_kernel<<<dim3(NCHUNK, BB), 160>>>();
    head_kernel<<<BB, 448>>>(W, bias, out);
}